// round 12
// baseline (speedup 1.0000x reference)
#include <cuda_runtime.h>

// Bilinear 2x upsample NHWC f32: (8,256,256,32) -> (8,512,512,32).
// Quad kernel, tight grid: interior quads only (j,k in [0,255], grid
// (8,256,8), all blocks full, no early-return). Degenerate edge outputs
// (col 511, row 511, corner) are folded into the adjacent interior threads,
// which already hold the required input values in registers:
//   col 511 = y-interp of input col 255 (vab/vbb of j=255 threads)
//   row 511 = x-interp of input row 255 (bL/bR of k=255 threads)
//   (511,511) = input (255,255) (vbb of the corner thread)
// Fixed fractions for scale 0.5; identical math to verified kernels.

#define IH 256
#define IW 256
#define OH 512
#define OW 512
#define C4 8          // 32 channels / 4 floats

__global__ __launch_bounds__(256) void bilinear2x_quad_tight_kernel(
    const float4* __restrict__ in, float4* __restrict__ out)
{
    // threadIdx.x: 8 channel-groups (c4, fastest) x 32 x-quads per block
    const int c4 = threadIdx.x & (C4 - 1);
    const int j  = blockIdx.x * 32 + (threadIdx.x >> 3);   // 0..255
    const int k  = blockIdx.y;                              // 0..255
    const int n  = blockIdx.z;

    // Input patch coords (clamped only at the 0 edge; j,k <= 255 here)
    const int ya = max(k - 1, 0);
    const int yb = k;
    const int xa = max(j - 1, 0);
    const int xb = j;

    const float4* __restrict__ ibase = in + (long long)n * (IH * IW * C4);
    const float4 vaa = __ldg(ibase + (ya * IW + xa) * C4 + c4);
    const float4 vab = __ldg(ibase + (ya * IW + xb) * C4 + c4);
    const float4 vba = __ldg(ibase + (yb * IW + xa) * C4 + c4);
    const float4 vbb = __ldg(ibase + (yb * IW + xb) * C4 + c4);

    // Separable x-interps: w_right = 0.25 (left out col), 0.75 (right out col)
    float4 tL, tR, bL, bR;
    tL.x = 0.75f * vaa.x + 0.25f * vab.x;  tR.x = 0.25f * vaa.x + 0.75f * vab.x;
    tL.y = 0.75f * vaa.y + 0.25f * vab.y;  tR.y = 0.25f * vaa.y + 0.75f * vab.y;
    tL.z = 0.75f * vaa.z + 0.25f * vab.z;  tR.z = 0.25f * vaa.z + 0.75f * vab.z;
    tL.w = 0.75f * vaa.w + 0.25f * vab.w;  tR.w = 0.25f * vaa.w + 0.75f * vab.w;
    bL.x = 0.75f * vba.x + 0.25f * vbb.x;  bR.x = 0.25f * vba.x + 0.75f * vbb.x;
    bL.y = 0.75f * vba.y + 0.25f * vbb.y;  bR.y = 0.25f * vba.y + 0.75f * vbb.y;
    bL.z = 0.75f * vba.z + 0.25f * vbb.z;  bR.z = 0.25f * vba.z + 0.75f * vbb.z;
    bL.w = 0.75f * vba.w + 0.25f * vbb.w;  bR.w = 0.25f * vba.w + 0.75f * vbb.w;

    // Output quad coords: r0/c0 clamped at 0 (j=0/k=0 quads write their
    // degenerate col/row twice with identical values); r1,c1 <= 510 here.
    const int r0 = max(2 * k - 1, 0);
    const int r1 = 2 * k;
    const int c0 = max(2 * j - 1, 0);
    const int c1 = 2 * j;

    float4* __restrict__ obase = out + (long long)n * (OH * OW * C4);

    float4 o;
    // (r0, c0): bottom weight 0.25
    o.x = 0.75f * tL.x + 0.25f * bL.x;
    o.y = 0.75f * tL.y + 0.25f * bL.y;
    o.z = 0.75f * tL.z + 0.25f * bL.z;
    o.w = 0.75f * tL.w + 0.25f * bL.w;
    obase[(r0 * OW + c0) * C4 + c4] = o;

    // (r0, c1)
    o.x = 0.75f * tR.x + 0.25f * bR.x;
    o.y = 0.75f * tR.y + 0.25f * bR.y;
    o.z = 0.75f * tR.z + 0.25f * bR.z;
    o.w = 0.75f * tR.w + 0.25f * bR.w;
    obase[(r0 * OW + c1) * C4 + c4] = o;

    // (r1, c0): bottom weight 0.75
    o.x = 0.25f * tL.x + 0.75f * bL.x;
    o.y = 0.25f * tL.y + 0.75f * bL.y;
    o.z = 0.25f * tL.z + 0.75f * bL.z;
    o.w = 0.25f * tL.w + 0.75f * bL.w;
    obase[(r1 * OW + c0) * C4 + c4] = o;

    // (r1, c1)
    o.x = 0.25f * tR.x + 0.75f * bR.x;
    o.y = 0.25f * tR.y + 0.75f * bR.y;
    o.z = 0.25f * tR.z + 0.75f * bR.z;
    o.w = 0.25f * tR.w + 0.75f * bR.w;
    obase[(r1 * OW + c1) * C4 + c4] = o;

    const bool jedge = (j == IW - 1);
    const bool kedge = (k == IH - 1);

    if (jedge) {
        // Output col 511, rows r0/r1: y-interp of input col 255 (vab, vbb)
        o.x = 0.75f * vab.x + 0.25f * vbb.x;
        o.y = 0.75f * vab.y + 0.25f * vbb.y;
        o.z = 0.75f * vab.z + 0.25f * vbb.z;
        o.w = 0.75f * vab.w + 0.25f * vbb.w;
        obase[(r0 * OW + (OW - 1)) * C4 + c4] = o;
        o.x = 0.25f * vab.x + 0.75f * vbb.x;
        o.y = 0.25f * vab.y + 0.75f * vbb.y;
        o.z = 0.25f * vab.z + 0.75f * vbb.z;
        o.w = 0.25f * vab.w + 0.75f * vbb.w;
        obase[(r1 * OW + (OW - 1)) * C4 + c4] = o;
    }
    if (kedge) {
        // Output row 511, cols c0/c1: x-interp of input row 255 (bL, bR)
        obase[((OH - 1) * OW + c0) * C4 + c4] = bL;
        obase[((OH - 1) * OW + c1) * C4 + c4] = bR;
        if (jedge) {
            // Corner (511, 511) = input (255, 255)
            obase[((OH - 1) * OW + (OW - 1)) * C4 + c4] = vbb;
        }
    }
}

extern "C" void kernel_launch(void* const* d_in, const int* in_sizes, int n_in,
                              void* d_out, int out_size)
{
    const float4* in  = (const float4*)d_in[0];
    float4*       out = (float4*)d_out;
    dim3 block(256, 1, 1);              // 8 c4 x 32 j
    dim3 grid(IW / 32, IH, 8);          // (8, 256, 8) — all blocks full
    bilinear2x_quad_tight_kernel<<<grid, block>>>(in, out);
}